// round 15
// baseline (speedup 1.0000x reference)
#include <cuda_runtime.h>
#include <cuda_fp16.h>
#include <cstdint>

// new_M = M + phi^T V - (phi^T phi) M ; new_z = z + colsum(phi); phi = elu(K)+1
// K,V: (64, 8192, 128) fp32 flattened over (b,h) -> contiguous (524288, 128).
// Phase0: zero per-bh accumulators + counters (4.2 MB, L2-resident).
// Phase1 (single fused kernel): persistent balanced mapping: 148 CTAs x ~110
//   32-row chunks. fp16 mma.sync: warps 0-7 G = phi^T phi (symmetric band
//   tiling), warps 8-15 A = phi^T V. Segment flush = atomicAdd into per-bh
//   G/A/z + chunk counter; the CTA completing a bh (counter hits 256) runs
//   the correction epilogue new_M = M + A - G*M, new_z inline.

#define NBH 64
#define NCTA 148
#define TOTCH 16384          // 64 bh * 256 chunks of 32 rows

__device__ float g_G[(size_t)NBH * 16384];
__device__ float g_A[(size_t)NBH * 16384];
__device__ float g_z[(size_t)NBH * 128];
__device__ int   g_cnt[NBH];

typedef unsigned long long u64;

// ---------------- helpers ----------------
__device__ __forceinline__ uint32_t smem_u32(const void* p) {
    uint32_t a;
    asm("{ .reg .u64 t; cvta.to.shared.u64 t, %1; cvt.u32.u64 %0, t; }"
        : "=r"(a) : "l"(p));
    return a;
}
__device__ __forceinline__ void ldsm4(uint32_t* r, uint32_t a) {
    asm volatile("ldmatrix.sync.aligned.m8n8.x4.shared.b16 {%0,%1,%2,%3}, [%4];"
                 : "=r"(r[0]), "=r"(r[1]), "=r"(r[2]), "=r"(r[3]) : "r"(a));
}
__device__ __forceinline__ void mma16816(float* c, const uint32_t* a,
                                         uint32_t b0, uint32_t b1) {
    asm volatile(
        "mma.sync.aligned.m16n8k16.row.col.f32.f16.f16.f32 "
        "{%0,%1,%2,%3}, {%4,%5,%6,%7}, {%8,%9}, {%0,%1,%2,%3};"
        : "+f"(c[0]), "+f"(c[1]), "+f"(c[2]), "+f"(c[3])
        : "r"(a[0]), "r"(a[1]), "r"(a[2]), "r"(a[3]), "r"(b0), "r"(b1));
}
__device__ __forceinline__ float phi_f(float x) {
    return x > 0.f ? x + 1.f : __expf(x);
}
__device__ __forceinline__ uint32_t packh2(float s1, float s0) {
    uint32_t r;  // low half <- s0, high half <- s1
    asm("cvt.rn.f16x2.f32 %0, %1, %2;" : "=r"(r) : "f"(s1), "f"(s0));
    return r;
}
// u32 index in an 8KB [d(128)][sq(16)] tile, XOR-swizzled on 16B groups
__device__ __forceinline__ int stoff(int d, int sq) {
    return (d << 4) + ((((sq >> 2) ^ ((d >> 1) & 3))) << 2) + (sq & 3);
}
// byte address for a 16B row-fragment: row d, 16B-group g
__device__ __forceinline__ uint32_t frag_addr(uint32_t base, int d, int g) {
    return base + (d << 6) + (((g ^ ((d >> 1) & 3))) << 4);
}
__device__ __forceinline__ u64 pk2(float x, float y) {
    u64 r; asm("mov.b64 %0,{%1,%2};" : "=l"(r) : "f"(x), "f"(y)); return r;
}
__device__ __forceinline__ void fma2(u64& c, u64 a, u64 b) {
    asm("fma.rn.f32x2 %0,%1,%2,%0;" : "+l"(c) : "l"(a), "l"(b));
}
__device__ __forceinline__ void add2(u64& c, u64 a) {
    asm("add.rn.f32x2 %0,%1,%0;" : "+l"(c) : "l"(a));
}

// ---------------------------------------------------------------------------
// Phase 0: zero accumulators + counters.
// ---------------------------------------------------------------------------
__global__ __launch_bounds__(512, 4)
void drp0_kernel() {
    const int i = blockIdx.x * 512 + threadIdx.x;   // grid 514 * 512
    if (i < 262144) {
        *(float4*)(g_G + (size_t)i * 4) = make_float4(0.f, 0.f, 0.f, 0.f);
        *(float4*)(g_A + (size_t)i * 4) = make_float4(0.f, 0.f, 0.f, 0.f);
    }
    if (i < 2048)
        *(float4*)(g_z + (size_t)i * 4) = make_float4(0.f, 0.f, 0.f, 0.f);
    if (i < NBH) g_cnt[i] = 0;
}

// ---------------------------------------------------------------------------
// Phase 1 (fused). grid NCTA, 512 threads.
// ---------------------------------------------------------------------------
__global__ __launch_bounds__(512, 1)
void drp1_kernel(const float* __restrict__ K, const float* __restrict__ V,
                 const float* __restrict__ M, const float* __restrict__ z,
                 float* __restrict__ out) {
    __shared__ uint32_t shm[8320];   // staging: smA 2x2048 | smB 2x2048 (32KB)
                                     // epilogue: GT 128*33 | Msh 128*32 (33KB)
    __shared__ int s_last;
    uint32_t* const smA = shm;            // [buf*2048 + idx]
    uint32_t* const smB = shm + 4096;

    const int cta = blockIdx.x;
    const int start = (cta * TOTCH) / NCTA;
    const int end   = ((cta + 1) * TOTCH) / NCTA;

    const int tid = threadIdx.x, w = tid >> 5, l = tid & 31;
    const int tg = w >> 3, w8 = w & 7;
    const int mb = (w8 & 1) * 64, nb = (w8 >> 1) * 32;      // A warps
    const int band = (w8 < 4) ? w8 : 11 - w8;               // G warps
    const int rbase = band * 16, ntlo = 2 * band;
    const int d2 = tid & 63;          // d-pair owner (staging)
    const int sq0 = tid >> 6;         // 0..7
    const int r = l >> 2, cc = 2 * (l & 3);

    const uint32_t baseA0 = smem_u32(shm), baseB0 = baseA0 + 16384;

    float accs[16][4];
    #pragma unroll
    for (int i = 0; i < 16; i++)
        #pragma unroll
        for (int qq = 0; qq < 4; qq++) accs[i][qq] = 0.f;
    float z0 = 0.f, z1 = 0.f;
    int b1 = ((start >> 8) + 1) << 8;   // next bh boundary chunk
    int segbeg = start;

    float2 kp[4], vp[4];

    // ---- prologue: load + convert chunk `start` into buf 0 ----
    {
        const float* Kc = K + (size_t)start * 4096;
        const float* Vc = V + (size_t)start * 4096;
        #pragma unroll
        for (int j = 0; j < 2; j++) {
            const float* kr = Kc + (size_t)((sq0 + 8 * j) << 1) * 128 + 2 * d2;
            const float* vr = Vc + (size_t)((sq0 + 8 * j) << 1) * 128 + 2 * d2;
            kp[2 * j] = __ldg((const float2*)kr);
            kp[2 * j + 1] = __ldg((const float2*)(kr + 128));
            vp[2 * j] = __ldg((const float2*)vr);
            vp[2 * j + 1] = __ldg((const float2*)(vr + 128));
        }
        #pragma unroll
        for (int j = 0; j < 2; j++) {
            const int sq = sq0 + 8 * j;
            float p00 = phi_f(kp[2 * j].x),     p01 = phi_f(kp[2 * j].y);
            float p10 = phi_f(kp[2 * j + 1].x), p11 = phi_f(kp[2 * j + 1].y);
            smA[stoff(2 * d2, sq)]     = packh2(p10, p00);
            smA[stoff(2 * d2 + 1, sq)] = packh2(p11, p01);
            z0 += p00 + p10;
            z1 += p01 + p11;
            smB[stoff(2 * d2, sq)]     = packh2(vp[2 * j + 1].x, vp[2 * j].x);
            smB[stoff(2 * d2 + 1, sq)] = packh2(vp[2 * j + 1].y, vp[2 * j].y);
        }
    }
    __syncthreads();

    for (int ch = start; ch < end; ch++) {
        const int buf = (ch - start) & 1, nbuf = buf ^ 1;
        const bool has_next = (ch + 1 < end);

        // ---- prefetch chunk ch+1 ----
        if (has_next) {
            const float* Kc = K + (size_t)(ch + 1) * 4096;
            const float* Vc = V + (size_t)(ch + 1) * 4096;
            #pragma unroll
            for (int j = 0; j < 2; j++) {
                const float* kr = Kc + (size_t)((sq0 + 8 * j) << 1) * 128 + 2 * d2;
                const float* vr = Vc + (size_t)((sq0 + 8 * j) << 1) * 128 + 2 * d2;
                kp[2 * j] = __ldg((const float2*)kr);
                kp[2 * j + 1] = __ldg((const float2*)(kr + 128));
                vp[2 * j] = __ldg((const float2*)vr);
                vp[2 * j + 1] = __ldg((const float2*)(vr + 128));
            }
        }

        // ---- mma on buf ----
        {
            const uint32_t bA = baseA0 + (uint32_t)buf * 8192;
            if (tg == 0) {
                // G band warp: rows [rbase,rbase+16), cols [16*band,128)
                #pragma unroll
                for (int ks = 0; ks < 2; ks++) {
                    const int g = 2 * ks + (l >> 4);
                    uint32_t af[4];
                    ldsm4(af, frag_addr(bA, rbase + (l & 15), g));
                    #pragma unroll
                    for (int p = 0; p < 8; p++) {
                        if (p >= band) {
                            uint32_t bb[4];
                            ldsm4(bb, frag_addr(bA, 16 * p + (l & 15), g));
                            mma16816(accs[2 * p],     af, bb[0], bb[2]);
                            mma16816(accs[2 * p + 1], af, bb[1], bb[3]);
                        }
                    }
                }
            } else {
                // A warp: 64x32 tile
                const uint32_t bOp = baseB0 + (uint32_t)buf * 8192;
                #pragma unroll
                for (int ks = 0; ks < 2; ks++) {
                    const int g = 2 * ks + (l >> 4);
                    uint32_t af[4][4];
                    #pragma unroll
                    for (int mt = 0; mt < 4; mt++)
                        ldsm4(af[mt], frag_addr(bA, mb + 16 * mt + (l & 15), g));
                    uint32_t bb[2][4];
                    #pragma unroll
                    for (int p = 0; p < 2; p++)
                        ldsm4(bb[p], frag_addr(bOp, nb + 16 * p + (l & 15), g));
                    #pragma unroll
                    for (int mt = 0; mt < 4; mt++)
                        #pragma unroll
                        for (int nt = 0; nt < 4; nt++)
                            mma16816(accs[mt * 4 + nt], af[mt],
                                     bb[nt >> 1][nt & 1], bb[nt >> 1][2 + (nt & 1)]);
                }
            }
        }

        // ---- segment flush (bh boundary or end of range) ----
        if (ch + 1 == b1 || ch + 1 == end) {
            const int fbh = ch >> 8;
            if (tg == 0) {
                float* dst = g_G + (size_t)fbh * 16384;
                const int row0 = rbase + r, row1 = rbase + r + 8;
                #pragma unroll
                for (int nt = 0; nt < 16; nt++) {
                    if (nt >= ntlo) {
                        const int col = 8 * nt + cc;
                        atomicAdd(dst + (size_t)row0 * 128 + col,     accs[nt][0]);
                        atomicAdd(dst + (size_t)row0 * 128 + col + 1, accs[nt][1]);
                        atomicAdd(dst + (size_t)row1 * 128 + col,     accs[nt][2]);
                        atomicAdd(dst + (size_t)row1 * 128 + col + 1, accs[nt][3]);
                        if (nt >= ntlo + 2) {   // mirror strict-upper into lower
                            atomicAdd(dst + (size_t)col * 128 + row0,       accs[nt][0]);
                            atomicAdd(dst + (size_t)(col + 1) * 128 + row0, accs[nt][1]);
                            atomicAdd(dst + (size_t)col * 128 + row1,       accs[nt][2]);
                            atomicAdd(dst + (size_t)(col + 1) * 128 + row1, accs[nt][3]);
                        }
                    }
                }
            } else {
                float* dst = g_A + (size_t)fbh * 16384;
                #pragma unroll
                for (int mt = 0; mt < 4; mt++)
                    #pragma unroll
                    for (int nt = 0; nt < 4; nt++) {
                        int row = mb + 16 * mt + r, col = nb + 8 * nt + cc;
                        atomicAdd(dst + (size_t)row * 128 + col,       accs[mt * 4 + nt][0]);
                        atomicAdd(dst + (size_t)row * 128 + col + 1,   accs[mt * 4 + nt][1]);
                        atomicAdd(dst + (size_t)(row + 8) * 128 + col,     accs[mt * 4 + nt][2]);
                        atomicAdd(dst + (size_t)(row + 8) * 128 + col + 1, accs[mt * 4 + nt][3]);
                    }
            }
            // z: 8 threads (sq0 groups) collide per d — atomic handles it
            atomicAdd(g_z + (size_t)fbh * 128 + 2 * d2,     z0);
            atomicAdd(g_z + (size_t)fbh * 128 + 2 * d2 + 1, z1);

            // ---- completion counter (release) ----
            __threadfence();
            __syncthreads();
            if (tid == 0) {
                int segch = (ch + 1) - segbeg;
                int old = atomicAdd(&g_cnt[fbh], segch);
                s_last = (old + segch == 256);
            }
            __syncthreads();

            // ---- last-flusher epilogue: new_M = M + A - G*M ; new_z ----
            if (s_last) {
                __threadfence();   // acquire
                const float* Mp = M + (size_t)fbh * 16384;
                const float* Ap = g_A + (size_t)fbh * 16384;
                const float* Gp = g_G + (size_t)fbh * 16384;
                float* GT  = (float*)shm;          // 128*33
                float* Msh = (float*)shm + 4224;   // 128*32
                float* outM = out + (size_t)fbh * 16384;
                const int tx = tid & 7, ty = tid >> 3;
                const int ra = ty * 2, cl = tx * 4;

                for (int q = 0; q < 4; q++) {
                    const int cb = q * 32 + cl;
                    __syncthreads();
                    for (int e = tid; e < 1024; e += 512) {
                        int row = e >> 3, c4 = (e & 7) * 4;
                        *(float4*)(Msh + row * 32 + c4) =
                            __ldg((const float4*)(Mp + (size_t)row * 128 + q * 32 + c4));
                    }
                    __syncthreads();

                    u64 acc2[2][2];
                    #pragma unroll
                    for (int i = 0; i < 2; i++)
                        #pragma unroll
                        for (int p = 0; p < 2; p++) {
                            size_t o = (size_t)(ra + i) * 128 + cb + 2 * p;
                            float2 m = *(const float2*)(Msh + (ra + i) * 32 + cl + 2 * p);
                            u64 a = pk2(m.x, m.y);
                            add2(a, *(const u64*)(Ap + o));
                            acc2[i][p] = a;
                        }

                    for (int ks = 0; ks < 128; ks += 32) {
                        __syncthreads();
                        for (int e = tid; e < 128 * 32; e += 512) {
                            int kk = e & 31, i = e >> 5;
                            GT[i * 33 + kk] = Gp[(size_t)i * 128 + ks + kk];
                        }
                        __syncthreads();

                        #pragma unroll 8
                        for (int kk = 0; kk < 32; kk++) {
                            int k = ks + kk;
                            float g0 = GT[(ra + 0) * 33 + kk];
                            float g1 = GT[(ra + 1) * 33 + kk];
                            float4 b = *(const float4*)(Msh + k * 32 + cl);
                            u64 b0 = pk2(b.x, b.y), bq1 = pk2(b.z, b.w);
                            u64 pa0 = pk2(-g0, -g0), pa1 = pk2(-g1, -g1);
                            fma2(acc2[0][0], pa0, b0);
                            fma2(acc2[0][1], pa0, bq1);
                            fma2(acc2[1][0], pa1, b0);
                            fma2(acc2[1][1], pa1, bq1);
                        }
                    }

                    #pragma unroll
                    for (int i = 0; i < 2; i++)
                        #pragma unroll
                        for (int p = 0; p < 2; p++)
                            *(u64*)(outM + (size_t)(ra + i) * 128 + cb + 2 * p) =
                                acc2[i][p];
                }

                if (tid < 128)
                    out[(size_t)NBH * 16384 + (size_t)fbh * 128 + tid] =
                        z[(size_t)fbh * 128 + tid] + g_z[(size_t)fbh * 128 + tid];
                __syncthreads();   // smem back to staging use
            }

            segbeg = ch + 1;
            b1 = 1 << 30;
            #pragma unroll
            for (int i = 0; i < 16; i++)
                #pragma unroll
                for (int qq = 0; qq < 4; qq++) accs[i][qq] = 0.f;
            z0 = z1 = 0.f;
        }

        // ---- convert + store chunk ch+1 into nbuf ----
        if (has_next) {
            #pragma unroll
            for (int j = 0; j < 2; j++) {
                const int sq = sq0 + 8 * j;
                float p00 = phi_f(kp[2 * j].x),     p01 = phi_f(kp[2 * j].y);
                float p10 = phi_f(kp[2 * j + 1].x), p11 = phi_f(kp[2 * j + 1].y);
                smA[nbuf * 2048 + stoff(2 * d2, sq)]     = packh2(p10, p00);
                smA[nbuf * 2048 + stoff(2 * d2 + 1, sq)] = packh2(p11, p01);
                z0 += p00 + p10;
                z1 += p01 + p11;
                smB[nbuf * 2048 + stoff(2 * d2, sq)]     = packh2(vp[2 * j + 1].x, vp[2 * j].x);
                smB[nbuf * 2048 + stoff(2 * d2 + 1, sq)] = packh2(vp[2 * j + 1].y, vp[2 * j].y);
            }
        }
        __syncthreads();
    }
}

extern "C" void kernel_launch(void* const* d_in, const int* in_sizes, int n_in,
                              void* d_out, int out_size) {
    const float* K = (const float*)d_in[0];
    const float* V = (const float*)d_in[1];
    const float* M = (const float*)d_in[2];
    const float* z = (const float*)d_in[3];
    float* out = (float*)d_out;

    drp0_kernel<<<514, 512>>>();
    drp1_kernel<<<NCTA, 512>>>(K, V, M, z, out);
}

// round 16
// speedup vs baseline: 1.1526x; 1.1526x over previous
#include <cuda_runtime.h>
#include <cuda_fp16.h>
#include <cstdint>

// new_M = M + phi^T V - (phi^T phi) M ; new_z = z + colsum(phi); phi = elu(K)+1
// K,V: (64, 8192, 128) fp32 flattened over (b,h) -> contiguous (524288, 128).
// Phase1: persistent balanced mapping: 148 CTAs x ~110 32-row chunks.
//   Fused fp16 mma.sync: warps 0-7 G = phi^T phi (symmetric band tiling),
//   warps 8-15 A = phi^T V. Segment flush = atomicAdd into per-bh G/A/z.
//   (Accumulators are zero at entry: zero-initialized on first call,
//    re-zeroed by phase2's self-cleaning tail on every call.)
// Phase2: single-source (L2-hot) new_M = M + A - G*M, new_z; then zero the
//   consumed accumulators for the next call (last-arriver zeroes G).

#define NBH 64
#define NCTA 148
#define TOTCH 16384          // 64 bh * 256 chunks of 32 rows

__device__ float g_G[(size_t)NBH * 16384];
__device__ float g_A[(size_t)NBH * 16384];
__device__ float g_z[(size_t)NBH * 128];
__device__ int   g_dcnt[NBH];

typedef unsigned long long u64;

// ---------------- helpers ----------------
__device__ __forceinline__ uint32_t smem_u32(const void* p) {
    uint32_t a;
    asm("{ .reg .u64 t; cvta.to.shared.u64 t, %1; cvt.u32.u64 %0, t; }"
        : "=r"(a) : "l"(p));
    return a;
}
__device__ __forceinline__ void ldsm4(uint32_t* r, uint32_t a) {
    asm volatile("ldmatrix.sync.aligned.m8n8.x4.shared.b16 {%0,%1,%2,%3}, [%4];"
                 : "=r"(r[0]), "=r"(r[1]), "=r"(r[2]), "=r"(r[3]) : "r"(a));
}
__device__ __forceinline__ void mma16816(float* c, const uint32_t* a,
                                         uint32_t b0, uint32_t b1) {
    asm volatile(
        "mma.sync.aligned.m16n8k16.row.col.f32.f16.f16.f32 "
        "{%0,%1,%2,%3}, {%4,%5,%6,%7}, {%8,%9}, {%0,%1,%2,%3};"
        : "+f"(c[0]), "+f"(c[1]), "+f"(c[2]), "+f"(c[3])
        : "r"(a[0]), "r"(a[1]), "r"(a[2]), "r"(a[3]), "r"(b0), "r"(b1));
}
__device__ __forceinline__ float phi_f(float x) {
    return x > 0.f ? x + 1.f : __expf(x);
}
__device__ __forceinline__ uint32_t packh2(float s1, float s0) {
    uint32_t r;  // low half <- s0, high half <- s1
    asm("cvt.rn.f16x2.f32 %0, %1, %2;" : "=r"(r) : "f"(s1), "f"(s0));
    return r;
}
// u32 index in an 8KB [d(128)][sq(16)] tile, XOR-swizzled on 16B groups
__device__ __forceinline__ int stoff(int d, int sq) {
    return (d << 4) + ((((sq >> 2) ^ ((d >> 1) & 3))) << 2) + (sq & 3);
}
// byte address for a 16B row-fragment: row d, 16B-group g
__device__ __forceinline__ uint32_t frag_addr(uint32_t base, int d, int g) {
    return base + (d << 6) + (((g ^ ((d >> 1) & 3))) << 4);
}

// ---------------------------------------------------------------------------
// Phase 1. grid NCTA, 512 threads, persistent balanced chunks.
// ---------------------------------------------------------------------------
__global__ __launch_bounds__(512, 1)
void drp1_kernel(const float* __restrict__ K, const float* __restrict__ V) {
    __shared__ uint32_t smA[2][2048];   // phi fp16x2 [d][sq] swizzled
    __shared__ uint32_t smB[2][2048];   // V   fp16x2 [d][sq] swizzled

    const int cta = blockIdx.x;
    const int start = (cta * TOTCH) / NCTA;
    const int end   = ((cta + 1) * TOTCH) / NCTA;

    const int tid = threadIdx.x, w = tid >> 5, l = tid & 31;
    const int tg = w >> 3, w8 = w & 7;
    const int mb = (w8 & 1) * 64, nb = (w8 >> 1) * 32;      // A warps
    const int band = (w8 < 4) ? w8 : 11 - w8;               // G warps
    const int rbase = band * 16, ntlo = 2 * band;
    const int d2 = tid & 63;          // d-pair owner (staging)
    const int sq0 = tid >> 6;         // 0..7
    const int r = l >> 2, cc = 2 * (l & 3);

    const uint32_t baseA0 = smem_u32(smA), baseB0 = smem_u32(smB);

    float accs[16][4];
    #pragma unroll
    for (int i = 0; i < 16; i++)
        #pragma unroll
        for (int qq = 0; qq < 4; qq++) accs[i][qq] = 0.f;
    float z0 = 0.f, z1 = 0.f;
    int b1 = ((start >> 8) + 1) << 8;   // next bh boundary chunk

    float2 kp[4], vp[4];

    // ---- prologue: load + convert chunk `start` into buf 0 ----
    {
        const float* Kc = K + (size_t)start * 4096;
        const float* Vc = V + (size_t)start * 4096;
        #pragma unroll
        for (int j = 0; j < 2; j++) {
            const float* kr = Kc + (size_t)((sq0 + 8 * j) << 1) * 128 + 2 * d2;
            const float* vr = Vc + (size_t)((sq0 + 8 * j) << 1) * 128 + 2 * d2;
            kp[2 * j] = __ldg((const float2*)kr);
            kp[2 * j + 1] = __ldg((const float2*)(kr + 128));
            vp[2 * j] = __ldg((const float2*)vr);
            vp[2 * j + 1] = __ldg((const float2*)(vr + 128));
        }
        #pragma unroll
        for (int j = 0; j < 2; j++) {
            const int sq = sq0 + 8 * j;
            float p00 = phi_f(kp[2 * j].x),     p01 = phi_f(kp[2 * j].y);
            float p10 = phi_f(kp[2 * j + 1].x), p11 = phi_f(kp[2 * j + 1].y);
            smA[0][stoff(2 * d2, sq)]     = packh2(p10, p00);
            smA[0][stoff(2 * d2 + 1, sq)] = packh2(p11, p01);
            z0 += p00 + p10;
            z1 += p01 + p11;
            smB[0][stoff(2 * d2, sq)]     = packh2(vp[2 * j + 1].x, vp[2 * j].x);
            smB[0][stoff(2 * d2 + 1, sq)] = packh2(vp[2 * j + 1].y, vp[2 * j].y);
        }
    }
    __syncthreads();

    for (int ch = start; ch < end; ch++) {
        const int buf = (ch - start) & 1, nbuf = buf ^ 1;
        const bool has_next = (ch + 1 < end);

        // ---- prefetch chunk ch+1 ----
        if (has_next) {
            const float* Kc = K + (size_t)(ch + 1) * 4096;
            const float* Vc = V + (size_t)(ch + 1) * 4096;
            #pragma unroll
            for (int j = 0; j < 2; j++) {
                const float* kr = Kc + (size_t)((sq0 + 8 * j) << 1) * 128 + 2 * d2;
                const float* vr = Vc + (size_t)((sq0 + 8 * j) << 1) * 128 + 2 * d2;
                kp[2 * j] = __ldg((const float2*)kr);
                kp[2 * j + 1] = __ldg((const float2*)(kr + 128));
                vp[2 * j] = __ldg((const float2*)vr);
                vp[2 * j + 1] = __ldg((const float2*)(vr + 128));
            }
        }

        // ---- mma on buf ----
        {
            const uint32_t bA = baseA0 + (uint32_t)buf * 8192;
            if (tg == 0) {
                // G band warp: rows [rbase,rbase+16), cols [16*band,128)
                #pragma unroll
                for (int ks = 0; ks < 2; ks++) {
                    const int g = 2 * ks + (l >> 4);
                    uint32_t af[4];
                    ldsm4(af, frag_addr(bA, rbase + (l & 15), g));
                    #pragma unroll
                    for (int p = 0; p < 8; p++) {
                        if (p >= band) {
                            uint32_t bb[4];
                            ldsm4(bb, frag_addr(bA, 16 * p + (l & 15), g));
                            mma16816(accs[2 * p],     af, bb[0], bb[2]);
                            mma16816(accs[2 * p + 1], af, bb[1], bb[3]);
                        }
                    }
                }
            } else {
                // A warp: 64x32 tile
                const uint32_t bOp = baseB0 + (uint32_t)buf * 8192;
                #pragma unroll
                for (int ks = 0; ks < 2; ks++) {
                    const int g = 2 * ks + (l >> 4);
                    uint32_t af[4][4];
                    #pragma unroll
                    for (int mt = 0; mt < 4; mt++)
                        ldsm4(af[mt], frag_addr(bA, mb + 16 * mt + (l & 15), g));
                    uint32_t bb[2][4];
                    #pragma unroll
                    for (int p = 0; p < 2; p++)
                        ldsm4(bb[p], frag_addr(bOp, nb + 16 * p + (l & 15), g));
                    #pragma unroll
                    for (int mt = 0; mt < 4; mt++)
                        #pragma unroll
                        for (int nt = 0; nt < 4; nt++)
                            mma16816(accs[mt * 4 + nt], af[mt],
                                     bb[nt >> 1][nt & 1], bb[nt >> 1][2 + (nt & 1)]);
                }
            }
        }

        // ---- segment flush (bh boundary or end of range): atomicAdd ----
        if (ch + 1 == b1 || ch + 1 == end) {
            const int fbh = ch >> 8;
            if (tg == 0) {
                float* dst = g_G + (size_t)fbh * 16384;
                const int row0 = rbase + r, row1 = rbase + r + 8;
                #pragma unroll
                for (int nt = 0; nt < 16; nt++) {
                    if (nt >= ntlo) {
                        const int col = 8 * nt + cc;
                        atomicAdd(dst + (size_t)row0 * 128 + col,     accs[nt][0]);
                        atomicAdd(dst + (size_t)row0 * 128 + col + 1, accs[nt][1]);
                        atomicAdd(dst + (size_t)row1 * 128 + col,     accs[nt][2]);
                        atomicAdd(dst + (size_t)row1 * 128 + col + 1, accs[nt][3]);
                        if (nt >= ntlo + 2) {   // mirror strict-upper into lower
                            atomicAdd(dst + (size_t)col * 128 + row0,       accs[nt][0]);
                            atomicAdd(dst + (size_t)(col + 1) * 128 + row0, accs[nt][1]);
                            atomicAdd(dst + (size_t)col * 128 + row1,       accs[nt][2]);
                            atomicAdd(dst + (size_t)(col + 1) * 128 + row1, accs[nt][3]);
                        }
                    }
                }
            } else {
                float* dst = g_A + (size_t)fbh * 16384;
                #pragma unroll
                for (int mt = 0; mt < 4; mt++)
                    #pragma unroll
                    for (int nt = 0; nt < 4; nt++) {
                        int row = mb + 16 * mt + r, col = nb + 8 * nt + cc;
                        atomicAdd(dst + (size_t)row * 128 + col,       accs[mt * 4 + nt][0]);
                        atomicAdd(dst + (size_t)row * 128 + col + 1,   accs[mt * 4 + nt][1]);
                        atomicAdd(dst + (size_t)(row + 8) * 128 + col,     accs[mt * 4 + nt][2]);
                        atomicAdd(dst + (size_t)(row + 8) * 128 + col + 1, accs[mt * 4 + nt][3]);
                    }
            }
            // z: 8 threads (sq0 groups) collide per d — atomic handles it
            atomicAdd(g_z + (size_t)fbh * 128 + 2 * d2,     z0);
            atomicAdd(g_z + (size_t)fbh * 128 + 2 * d2 + 1, z1);

            b1 = 1 << 30;
            #pragma unroll
            for (int i = 0; i < 16; i++)
                #pragma unroll
                for (int qq = 0; qq < 4; qq++) accs[i][qq] = 0.f;
            z0 = z1 = 0.f;
        }

        // ---- convert + store chunk ch+1 into nbuf ----
        if (has_next) {
            #pragma unroll
            for (int j = 0; j < 2; j++) {
                const int sq = sq0 + 8 * j;
                float p00 = phi_f(kp[2 * j].x),     p01 = phi_f(kp[2 * j].y);
                float p10 = phi_f(kp[2 * j + 1].x), p11 = phi_f(kp[2 * j + 1].y);
                smA[nbuf][stoff(2 * d2, sq)]     = packh2(p10, p00);
                smA[nbuf][stoff(2 * d2 + 1, sq)] = packh2(p11, p01);
                z0 += p00 + p10;
                z1 += p01 + p11;
                smB[nbuf][stoff(2 * d2, sq)]     = packh2(vp[2 * j + 1].x, vp[2 * j].x);
                smB[nbuf][stoff(2 * d2 + 1, sq)] = packh2(vp[2 * j + 1].y, vp[2 * j].y);
            }
        }
        __syncthreads();
    }
}

// ---------------------------------------------------------------------------
// Phase 2: new_M = M + A - G*M ; new_z. grid (64, 4), 512 threads.
// Single L2-hot source per bh. Self-cleaning: zeroes consumed accumulators.
// ---------------------------------------------------------------------------
__device__ __forceinline__ u64 pk2(float x, float y) {
    u64 r; asm("mov.b64 %0,{%1,%2};" : "=l"(r) : "f"(x), "f"(y)); return r;
}
__device__ __forceinline__ void fma2(u64& c, u64 a, u64 b) {
    asm("fma.rn.f32x2 %0,%1,%2,%0;" : "+l"(c) : "l"(a), "l"(b));
}
__device__ __forceinline__ void add2(u64& c, u64 a) {
    asm("add.rn.f32x2 %0,%1,%0;" : "+l"(c) : "l"(a));
}

__global__ __launch_bounds__(512, 2)
void drp2_kernel(const float* __restrict__ M, const float* __restrict__ z,
                 float* __restrict__ out) {
    const int bh = blockIdx.x, q = blockIdx.y;
    __shared__ float GT[128 * 33];    // GT[i][kk], pad 33
    __shared__ float Msh[128 * 32];   // M[:, q*32 : q*32+32]
    __shared__ int s_last;

    const int tid = threadIdx.x;
    const int tx = tid & 7, ty = tid >> 3;    // 8 col-groups x 64 row-groups
    const int ra = ty * 2;                    // 2 rows
    const int cl = tx * 4;                    // local col (0..28)
    const int cb = q * 32 + cl;               // global col

    const float* Mp = M + (size_t)bh * 16384;
    const float* Ap = g_A + (size_t)bh * 16384;
    const float* Gp = g_G + (size_t)bh * 16384;

    // stage M slice
    for (int e = tid; e < 1024; e += 512) {
        int row = e >> 3, c4 = (e & 7) * 4;
        *(float4*)(Msh + row * 32 + c4) =
            __ldg((const float4*)(Mp + (size_t)row * 128 + q * 32 + c4));
    }
    __syncthreads();

    u64 acc[2][2];
    #pragma unroll
    for (int i = 0; i < 2; i++) {
        #pragma unroll
        for (int p = 0; p < 2; p++) {
            size_t o = (size_t)(ra + i) * 128 + cb + 2 * p;
            float2 m = *(const float2*)(Msh + (ra + i) * 32 + cl + 2 * p);
            u64 a = pk2(m.x, m.y);
            add2(a, *(const u64*)(Ap + o));
            acc[i][p] = a;
        }
    }

    for (int ks = 0; ks < 128; ks += 32) {
        __syncthreads();
        for (int e = tid; e < 128 * 32; e += 512) {
            int kk = e & 31, i = e >> 5;
            GT[i * 33 + kk] = Gp[(size_t)i * 128 + ks + kk];
        }
        __syncthreads();

        #pragma unroll 8
        for (int kk = 0; kk < 32; kk++) {
            int k = ks + kk;
            float g0 = GT[(ra + 0) * 33 + kk];
            float g1 = GT[(ra + 1) * 33 + kk];
            float4 b = *(const float4*)(Msh + k * 32 + cl);
            u64 b0 = pk2(b.x, b.y), b1 = pk2(b.z, b.w);
            u64 pa0 = pk2(-g0, -g0), pa1 = pk2(-g1, -g1);
            fma2(acc[0][0], pa0, b0);
            fma2(acc[0][1], pa0, b1);
            fma2(acc[1][0], pa1, b0);
            fma2(acc[1][1], pa1, b1);
        }
    }

    float* outM = out + (size_t)bh * 16384;
    #pragma unroll
    for (int i = 0; i < 2; i++)
        #pragma unroll
        for (int p = 0; p < 2; p++)
            *(u64*)(outM + (size_t)(ra + i) * 128 + cb + 2 * p) = acc[i][p];

    if (q == 0 && tid < 128) {
        out[(size_t)NBH * 16384 + (size_t)bh * 128 + tid] =
            z[(size_t)bh * 128 + tid] + g_z[(size_t)bh * 128 + tid];
    }

    // ---- self-cleaning: restore zero invariant for next call ----
    // A quarter (cols [q*32, q*32+32)) is read only by this CTA: zero it.
    __syncthreads();   // all reads of Ap/g_z by this CTA complete
    for (int e = tid; e < 1024; e += 512) {
        int row = e >> 3, c4 = (e & 7) * 4;
        *(float4*)(g_A + (size_t)bh * 16384 + (size_t)row * 128 + q * 32 + c4) =
            make_float4(0.f, 0.f, 0.f, 0.f);
    }
    if (q == 0 && tid < 32)
        *(float4*)(g_z + (size_t)bh * 128 + tid * 4) =
            make_float4(0.f, 0.f, 0.f, 0.f);

    // G is read by all 4 q-CTAs: the last arriver zeroes it + resets counter.
    __threadfence();
    if (tid == 0) s_last = (atomicAdd(&g_dcnt[bh], 1) == 3);
    __syncthreads();
    if (s_last) {
        for (int e = tid; e < 4096; e += 512)
            *(float4*)(g_G + (size_t)bh * 16384 + (size_t)e * 4) =
                make_float4(0.f, 0.f, 0.f, 0.f);
        if (tid == 0) g_dcnt[bh] = 0;
    }
}

extern "C" void kernel_launch(void* const* d_in, const int* in_sizes, int n_in,
                              void* d_out, int out_size) {
    const float* K = (const float*)d_in[0];
    const float* V = (const float*)d_in[1];
    const float* M = (const float*)d_in[2];
    const float* z = (const float*)d_in[3];
    float* out = (float*)d_out;

    drp1_kernel<<<NCTA, 512>>>(K, V);
    drp2_kernel<<<dim3(NBH, 4), 512>>>(M, z, out);
}